// round 12
// baseline (speedup 1.0000x reference)
#include <cuda_runtime.h>
#include <cuda_bf16.h>
#include <cstdint>
#include <cmath>

// Problem: B=64, T=512, E=256, U=256, bidirectional LSTM (all-tanh), mask carry.

// ---------------------------------------------------------------------------
// Device scratch
// ---------------------------------------------------------------------------
__device__ float g_Z[2ull * 512 * 64 * 1024];                  // [dir][t][b][u*4+g]
__device__ unsigned char g_mask[64 * 512];                     // [b][t]
__device__ __align__(16) __nv_bfloat16 g_Xhi[32768ull * 256];  // [m=t*64+b][k]
__device__ __align__(16) __nv_bfloat16 g_Xlo[32768ull * 256];
__device__ __align__(16) __nv_bfloat16 g_Whi[2ull * 1024 * 256]; // [dir][q=u*4+g][k]
__device__ __align__(16) __nv_bfloat16 g_Wlo[2ull * 1024 * 256];

// ---------------------------------------------------------------------------
// PTX helpers (family-level features only)
// ---------------------------------------------------------------------------
__device__ __forceinline__ uint32_t smem_u32(const void* p)
{
    uint32_t a;
    asm("{ .reg .u64 t; cvta.to.shared.u64 t, %1; cvt.u32.u64 %0, t; }"
        : "=r"(a) : "l"(p));
    return a;
}

#define CP_ASYNC16(dst, src) \
    asm volatile("cp.async.cg.shared.global [%0], [%1], 16;" \
                 :: "r"(dst), "l"(src) : "memory")
#define CP_ASYNC_COMMIT() asm volatile("cp.async.commit_group;" ::: "memory")
#define CP_ASYNC_WAIT(n)  asm volatile("cp.async.wait_group %0;" :: "n"(n) : "memory")

__device__ __forceinline__ void ldm4(uint32_t* r, uint32_t addr)
{
    asm volatile("ldmatrix.sync.aligned.m8n8.x4.shared.b16 {%0,%1,%2,%3}, [%4];"
                 : "=r"(r[0]), "=r"(r[1]), "=r"(r[2]), "=r"(r[3]) : "r"(addr));
}

__device__ __forceinline__ void mma16816(float* c, const uint32_t* a,
                                         uint32_t b0, uint32_t b1)
{
    asm volatile(
        "mma.sync.aligned.m16n8k16.row.col.f32.bf16.bf16.f32 "
        "{%0,%1,%2,%3}, {%4,%5,%6,%7}, {%8,%9}, {%0,%1,%2,%3};"
        : "+f"(c[0]), "+f"(c[1]), "+f"(c[2]), "+f"(c[3])
        : "r"(a[0]), "r"(a[1]), "r"(a[2]), "r"(a[3]), "r"(b0), "r"(b1));
}

__device__ __forceinline__ uint32_t mapa_rank(uint32_t addr, uint32_t rank)
{
    uint32_t r;
    asm("mapa.shared::cluster.u32 %0, %1, %2;" : "=r"(r) : "r"(addr), "r"(rank));
    return r;
}
#define ST_CLUSTER_U32(addr, v) \
    asm volatile("st.shared::cluster.u32 [%0], %1;" :: "r"(addr), "r"(v) : "memory")

#define MBARRIER_INIT(addr, count) \
    asm volatile("mbarrier.init.shared.b64 [%0], %1;" \
                 :: "r"((uint32_t)(addr)), "r"((uint32_t)(count)) : "memory")
#define MBAR_ARRIVE_REL_CLUSTER(addr) \
    asm volatile("mbarrier.arrive.release.cluster.shared::cluster.b64 _, [%0];" \
                 :: "r"((uint32_t)(addr)) : "memory")

#define MBAR_WAIT_ACQ_CLUSTER(mbar, parity) do { \
    uint32_t _m = (uint32_t)(mbar); \
    uint32_t _p = (uint32_t)(parity); \
    uint32_t _done; \
    asm volatile( \
        "{\n\t.reg .pred p;\n\t" \
        "mbarrier.try_wait.parity.acquire.cluster.shared::cta.b64 p, [%1], %2;\n\t" \
        "selp.b32 %0, 1, 0, p;\n\t}" \
        : "=r"(_done) : "r"(_m), "r"(_p) : "memory"); \
    if (!_done) { \
        asm volatile( \
            "{\n\t.reg .pred P1;\n\t" \
            "WL_%=:\n\t" \
            "mbarrier.try_wait.parity.acquire.cluster.shared::cta.b64 P1, [%0], %1, 0x989680;\n\t" \
            "@P1 bra.uni WD_%=;\n\t" \
            "bra.uni WL_%=;\n\t" \
            "WD_%=:\n\t}" \
            :: "r"(_m), "r"(_p) : "memory"); \
    } \
} while (0)

#define CLUSTER_SYNC() do { \
    asm volatile("barrier.cluster.arrive.aligned;" ::: "memory"); \
    asm volatile("barrier.cluster.wait.aligned;"   ::: "memory"); \
} while (0)

// Fast tanh: 1 - 2/(e^{2x}+1)  (MUFU path; rel err ~1e-6, exact saturation).
__device__ __forceinline__ float ftanh(float x)
{
    float e = __expf(2.f * x);
    return 1.f - __fdividef(2.f, e + 1.f);
}

__device__ __forceinline__ uint32_t swz512(uint32_t row, uint32_t kb)
{
    return row * 512 + (kb & 0x180u) + ((kb & 0x70u) ^ ((row & 7u) << 4)) + (kb & 0xFu);
}

// ---------------------------------------------------------------------------
// Mask kernel: mask[b][t] = any(x[b,t,:] != 0)
// ---------------------------------------------------------------------------
__global__ void mask_kernel(const float* __restrict__ x)
{
    int gw   = (blockIdx.x * blockDim.x + threadIdx.x) >> 5;
    int lane = threadIdx.x & 31;
    if (gw >= 64 * 512) return;
    const float4* p = reinterpret_cast<const float4*>(x + (size_t)gw * 256);
    float4 a = p[lane];
    float4 b = p[lane + 32];
    bool nz = (a.x != 0.f) || (a.y != 0.f) || (a.z != 0.f) || (a.w != 0.f) ||
              (b.x != 0.f) || (b.y != 0.f) || (b.z != 0.f) || (b.w != 0.f);
    unsigned m = __ballot_sync(0xffffffffu, nz);
    if (lane == 0) g_mask[gw] = (m != 0u) ? 1 : 0;
}

// ---------------------------------------------------------------------------
// Converters: fp32 -> (hi, lo) bf16 split
// ---------------------------------------------------------------------------
__device__ __forceinline__ void split_bf16(float f, __nv_bfloat16& hi, __nv_bfloat16& lo)
{
    hi = __float2bfloat16_rn(f);
    lo = __float2bfloat16_rn(f - __bfloat162float(hi));
}

__global__ __launch_bounds__(256) void convert_x_kernel(const float* __restrict__ x)
{
    uint32_t idx = blockIdx.x * 256u + threadIdx.x;   // 2,097,152 total
    int m = idx >> 6, q = idx & 63;
    int b = m & 63, t = m >> 6;
    float4 v = *reinterpret_cast<const float4*>(x + ((size_t)b * 512 + t) * 256 + q * 4);
    __nv_bfloat16 h0, h1, h2, h3, l0, l1, l2, l3;
    split_bf16(v.x, h0, l0);
    split_bf16(v.y, h1, l1);
    split_bf16(v.z, h2, l2);
    split_bf16(v.w, h3, l3);
    __nv_bfloat162 hp0(h0, h1), hp1(h2, h3), lp0(l0, l1), lp1(l2, l3);
    uint2 hv, lv;
    hv.x = *reinterpret_cast<uint32_t*>(&hp0);
    hv.y = *reinterpret_cast<uint32_t*>(&hp1);
    lv.x = *reinterpret_cast<uint32_t*>(&lp0);
    lv.y = *reinterpret_cast<uint32_t*>(&lp1);
    *reinterpret_cast<uint2*>(g_Xhi + (size_t)m * 256 + q * 4) = hv;
    *reinterpret_cast<uint2*>(g_Xlo + (size_t)m * 256 + q * 4) = lv;
}

__global__ __launch_bounds__(256) void convert_w_kernel(
    const float* __restrict__ Wk_f, const float* __restrict__ Wk_b)
{
    uint32_t idx = blockIdx.x * 256u + threadIdx.x;   // 524,288 total
    int dir = idx >> 18;
    uint32_t rem = idx & 0x3FFFFu;
    int q = rem >> 8, k = rem & 255;
    int u = q >> 2, g = q & 3;
    float v = (dir ? Wk_b : Wk_f)[k * 1024 + g * 256 + u];
    __nv_bfloat16 hi, lo;
    split_bf16(v, hi, lo);
    g_Whi[idx] = hi;
    g_Wlo[idx] = lo;
}

// ---------------------------------------------------------------------------
// Input GEMM via mma.sync bf16 split-3 (proven: ~255us, tensor 67%)
// ---------------------------------------------------------------------------
#define GEMM_STAGE_BYTES 65536
#define GEMM_SMEM_BYTES  (2 * GEMM_STAGE_BYTES + 1024)

__global__ __launch_bounds__(256, 1) void gemm_mma_kernel(
    const float* __restrict__ b_f, const float* __restrict__ b_b)
{
    extern __shared__ char smc[];
    char* stages = smc;
    float* bias_s = reinterpret_cast<float*>(smc + 2 * GEMM_STAGE_BYTES);
    const uint32_t st_u32 = smem_u32(stages);

    const int tid  = threadIdx.x;
    const int wid  = tid >> 5, lane = tid & 31;
    const int wm   = wid & 3, wn = wid >> 2;
    const int mt   = blockIdx.x * 128;
    const int nt   = blockIdx.y;
    const int dir  = nt >> 3;
    const int q0   = (nt & 7) * 128;

    if (tid < 128) {
        const int q = q0 + tid;
        bias_s[tid] = (dir ? b_b : b_f)[(q & 3) * 256 + (q >> 2)];
    }

    const char* srcs[4] = {
        reinterpret_cast<const char*>(g_Xhi),
        reinterpret_cast<const char*>(g_Xlo),
        reinterpret_cast<const char*>(g_Whi),
        reinterpret_cast<const char*>(g_Wlo)
    };

    auto load_chunk = [&](int c, int s) {
        const uint32_t sb = st_u32 + (uint32_t)s * GEMM_STAGE_BYTES;
        const int koff = c * 128;
#pragma unroll
        for (int it = 0; it < 16; it++) {
            const int idx    = it * 256 + tid;
            const int region = idx >> 10;
            const int r      = (idx >> 3) & 127;
            const int q4     = idx & 7;
            const int grow   = (region < 2) ? (mt + r) : (dir * 1024 + q0 + r);
            const char* src  = srcs[region] + (size_t)grow * 512 + koff + q4 * 16;
            const uint32_t dst = sb + region * 16384 + r * 128
                               + (((uint32_t)q4 * 16) ^ (((uint32_t)(r & 7)) * 16));
            CP_ASYNC16(dst, src);
        }
    };

    const int grp = lane >> 3, lr = lane & 7;
    const uint32_t xr16 = (uint32_t)lr * 16;
    const uint32_t koffA = (uint32_t)(grp >> 1) * 16;
    const uint32_t koffB = (uint32_t)(grp & 1) * 16;
    uint32_t baseA[2], baseB[4];
#pragma unroll
    for (int i = 0; i < 2; i++) {
        const int rowA = wm * 32 + i * 16 + lr + (grp & 1) * 8;
        baseA[i] = (uint32_t)rowA * 128;
    }
#pragma unroll
    for (int j2 = 0; j2 < 4; j2++) {
        const int rowB = wn * 64 + j2 * 16 + lr + (grp >> 1) * 8;
        baseB[j2] = (uint32_t)rowB * 128;
    }

    float acc[2][8][4];
#pragma unroll
    for (int i = 0; i < 2; i++)
#pragma unroll
        for (int j = 0; j < 8; j++)
#pragma unroll
            for (int v = 0; v < 4; v++) acc[i][j][v] = 0.f;

    load_chunk(0, 0);
    CP_ASYNC_COMMIT();

#pragma unroll
    for (int c = 0; c < 4; c++) {
        if (c < 3) { load_chunk(c + 1, (c + 1) & 1); CP_ASYNC_COMMIT(); }
        if (c < 3) CP_ASYNC_WAIT(1); else CP_ASYNC_WAIT(0);
        __syncthreads();

        const uint32_t sb = st_u32 + (uint32_t)(c & 1) * GEMM_STAGE_BYTES;
        const uint32_t Ah = sb, Al = sb + 16384, Bh = sb + 32768, Bl = sb + 49152;

#pragma unroll
        for (int ks = 0; ks < 4; ks++) {
            const uint32_t offA = (((uint32_t)ks * 32) + koffA) ^ xr16;
            const uint32_t offB = (((uint32_t)ks * 32) + koffB) ^ xr16;
            uint32_t ah[2][4], al[2][4], bh[4][4], bl[4][4];
#pragma unroll
            for (int i = 0; i < 2; i++) {
                ldm4(ah[i], Ah + baseA[i] + offA);
                ldm4(al[i], Al + baseA[i] + offA);
            }
#pragma unroll
            for (int j2 = 0; j2 < 4; j2++) {
                ldm4(bh[j2], Bh + baseB[j2] + offB);
                ldm4(bl[j2], Bl + baseB[j2] + offB);
            }
#pragma unroll
            for (int i = 0; i < 2; i++)
#pragma unroll
                for (int j = 0; j < 8; j++) {
                    const int j2 = j >> 1, sel = (j & 1) * 2;
                    mma16816(acc[i][j], ah[i], bh[j2][sel], bh[j2][sel + 1]);
                    mma16816(acc[i][j], ah[i], bl[j2][sel], bl[j2][sel + 1]);
                    mma16816(acc[i][j], al[i], bh[j2][sel], bh[j2][sel + 1]);
                }
        }
        __syncthreads();
    }

    const int mrow0 = mt + wm * 32 + (lane >> 2);
    const int qcol0 = q0 + wn * 64 + (lane & 3) * 2;
#pragma unroll
    for (int i = 0; i < 2; i++) {
#pragma unroll
        for (int j = 0; j < 8; j++) {
            const int q  = qcol0 + j * 8;
            const float bx = bias_s[q - q0], by = bias_s[q - q0 + 1];
#pragma unroll
            for (int half = 0; half < 2; half++) {
                const int m  = mrow0 + i * 16 + half * 8;
                const int bb = m & 63, tt = m >> 6;
                float2 v;
                v.x = acc[i][j][half * 2 + 0] + bx;
                v.y = acc[i][j][half * 2 + 1] + by;
                *reinterpret_cast<float2*>(
                    g_Z + (((size_t)dir * 512 + tt) * 64 + bb) * 1024 + q) = v;
            }
        }
    }
}

// ---------------------------------------------------------------------------
// Recurrence (cluster of 8) — R10 structure verbatim (measured 2314us total).
// 64 CTAs = 2 dirs x 4 batch-groups(16) x 8 cluster ranks.
// ---------------------------------------------------------------------------
#define RP_WHI   0
#define RP_WLO   65536
#define RP_A     131072
#define RP_MASK  196608
#define RP_BAR   204800
#define RP_SMEM  204864

__global__ void __cluster_dims__(8, 1, 1) __launch_bounds__(256, 1)
lstm_rec8_kernel(const float* __restrict__ Wr_f, const float* __restrict__ Wr_b,
                 float* __restrict__ out)
{
    extern __shared__ char smr[];
    const uint32_t sbase = smem_u32(smr);
    unsigned char* m_s = reinterpret_cast<unsigned char*>(smr + RP_MASK);

    const int tid  = threadIdx.x;
    const int bx   = blockIdx.x;
    const int dir  = bx >> 5;
    const int bgrp = (bx >> 3) & 3;
    const int rank = bx & 7;
    const int w    = tid >> 5, lane = tid & 31;
    const int b    = lane >> 2;
    const int q    = lane & 3;
    const int mg   = lane >> 3, lr = lane & 7;

    const int u_l  = 4 * w + (q >> 1) + 2 * (q & 1);
    const int ug   = (rank << 5) + u_l;

    const float* Wr = dir ? Wr_b : Wr_f;
    for (int i = tid; i < 32768; i += 256) {
        const int n = i & 127;
        const int k = i >> 7;
        const float v = __ldg(&Wr[k * 1024 + (n & 3) * 256 + (rank << 5) + (n >> 2)]);
        __nv_bfloat16 hi, lo;
        split_bf16(v, hi, lo);
        const uint32_t off = swz512((uint32_t)n, (uint32_t)(k * 2));
        *reinterpret_cast<__nv_bfloat16*>(smr + RP_WHI + off) = hi;
        *reinterpret_cast<__nv_bfloat16*>(smr + RP_WLO + off) = lo;
    }
    for (int i = tid; i < 4096; i += 256)
        reinterpret_cast<float4*>(smr + RP_A)[i] = make_float4(0.f, 0.f, 0.f, 0.f);
    for (int i = tid; i < 16 * 512; i += 256)
        m_s[i] = g_mask[(bgrp * 16 + (i >> 9)) * 512 + (i & 511)];
    if (tid == 0) {
        MBARRIER_INIT(sbase + RP_BAR + 0, 8);
        MBARRIER_INIT(sbase + RP_BAR + 8, 8);
        MBARRIER_INIT(sbase + RP_BAR + 16, 8);
        MBARRIER_INIT(sbase + RP_BAR + 24, 8);
    }
    __syncthreads();
    CLUSTER_SYNC();

    uint32_t rbar = 0;
    if (tid < 8) {
        rbar = mapa_rank(sbase + RP_BAR, (uint32_t)tid);
        MBAR_ARRIVE_REL_CLUSTER(rbar);
        MBAR_ARRIVE_REL_CLUSTER(rbar + 16);
    }

    const uint32_t awoff = swz512((uint32_t)b, (uint32_t)(2 * (ug & ~1)));
    uint32_t rA[8];
#pragma unroll
    for (int r = 0; r < 8; r++) rA[r] = mapa_rank(sbase + RP_A + awoff, (uint32_t)r);

    const uint32_t rowA  = (uint32_t)(lr + (mg & 1) * 8);
    const uint32_t koffA = (uint32_t)((mg >> 1) * 16);
    const uint32_t rowB  = (uint32_t)(w * 16 + lr + (mg >> 1) * 8);
    const uint32_t koffB = (uint32_t)((mg & 1) * 16);
    const uint32_t swA   = (uint32_t)lr << 4;
    const uint32_t baseBhi = sbase + RP_WHI + rowB * 512;
    const uint32_t baseBlo = sbase + RP_WLO + rowB * 512;

    const float4* Z4 = reinterpret_cast<const float4*>(g_Z);
    const int t0 = dir ? 511 : 0;

    float cstA = 0.f, hprevA = 0.f, hlastA = 0.f;
    float cstB = 0.f, hprevB = 0.f, hlastB = 0.f;
    const int bgA = bgrp * 16 + b;
    const int bgB = bgA + 8;
    float4 znA = __ldg(&Z4[(((size_t)dir * 512 + t0) * 64 + bgA) * 256 + ug]);
    float4 znB = __ldg(&Z4[(((size_t)dir * 512 + t0) * 64 + bgB) * 256 + ug]);

    for (int step = 0; step < 512; step++) {
        const int t   = dir ? (511 - step) : step;
        const int cur = step & 1;
        const int nxt = cur ^ 1;
        const uint32_t par = (uint32_t)(step >> 1) & 1u;
        const int tn = dir ? (510 - step) : (step + 1);

#pragma unroll
        for (int ch = 0; ch < 2; ch++) {
            MBAR_WAIT_ACQ_CLUSTER(sbase + RP_BAR + ch * 16 + cur * 8, par);

            float4 zin = ch ? znB : znA;
            if (step < 511) {
                const int bgl = ch ? bgB : bgA;
                float4 z = __ldg(&Z4[(((size_t)dir * 512 + tn) * 64 + bgl) * 256 + ug]);
                if (ch) znB = z; else znA = z;
            }

            const uint32_t abase = sbase + RP_A + (uint32_t)ch * 32768
                                 + (uint32_t)cur * 16384;
            const uint32_t baseAhi = abase + rowA * 512;
            const uint32_t baseAlo = baseAhi + 8192;
            float a0[4] = {0.f, 0.f, 0.f, 0.f};
            float b0[4] = {0.f, 0.f, 0.f, 0.f};
            float c0v[4] = {0.f, 0.f, 0.f, 0.f};
            float a1[4] = {0.f, 0.f, 0.f, 0.f};
            float b1[4] = {0.f, 0.f, 0.f, 0.f};
            float c1v[4] = {0.f, 0.f, 0.f, 0.f};
#pragma unroll
            for (int kt = 0; kt < 16; kt++) {
                const uint32_t kbA = (uint32_t)kt * 32 + koffA;
                const uint32_t kbB = (uint32_t)kt * 32 + koffB;
                const uint32_t offA = (kbA & 0x180u) + ((kbA & 0x70u) ^ swA);
                const uint32_t offB = (kbB & 0x180u) + ((kbB & 0x70u) ^ swA);
                uint32_t ah[4], al[4], bh[4], bl[4];
                ldm4(ah, baseAhi + offA);
                ldm4(al, baseAlo + offA);
                ldm4(bh, baseBhi + offB);
                ldm4(bl, baseBlo + offB);
                mma16816(a0, ah, bh[0], bh[1]);
                mma16816(b0, ah, bl[0], bl[1]);
                mma16816(c0v, al, bh[0], bh[1]);
                mma16816(a1, ah, bh[2], bh[3]);
                mma16816(b1, ah, bl[2], bl[3]);
                mma16816(c1v, al, bh[2], bh[3]);
            }
            const float c0 = a0[0] + b0[0] + c0v[0];
            const float c1 = a0[1] + b0[1] + c0v[1];
            const float d0 = a1[0] + b1[0] + c1v[0];
            const float d1 = a1[1] + b1[1] + c1v[1];

            const bool odd = (q & 1) != 0;
            const float s0 = odd ? c0 : d0;
            const float s1 = odd ? c1 : d1;
            const float r0 = __shfl_xor_sync(0xffffffffu, s0, 1);
            const float r1 = __shfl_xor_sync(0xffffffffu, s1, 1);
            float zi = (odd ? r0 : c0) + zin.x;
            float zf = (odd ? r1 : c1) + zin.y;
            float zc = (odd ? d0 : r0) + zin.z;
            float zo = (odd ? d1 : r1) + zin.w;

            const float gi = ftanh(zi);
            const float gf = ftanh(zf);
            const float gc = ftanh(zc);
            const float go = ftanh(zo);
            const float cstp = ch ? cstB : cstA;
            const float hpp  = ch ? hprevB : hprevA;
            const float cn = fmaf(gf, cstp, gi * gc);
            const float hn = go * ftanh(cn);

            const int  mrow = ch ? (b + 8) : b;
            const bool mk = m_s[(mrow << 9) + t] != 0;
            const float hv = mk ? hn : hpp;
            const float cv = mk ? cn : cstp;
            if (ch) { cstB = cv; hprevB = hv; hlastB = hv; }
            else    { cstA = cv; hprevA = hv; hlastA = hv; }

            const int bgl = ch ? bgB : bgA;
            out[((size_t)bgl * 512 + t) * 512 + (dir << 8) + ug] = hv;

            const float hvp = __shfl_xor_sync(0xffffffffu, hv, 2);
            if (q < 2) {
                __nv_bfloat16 he, le, ho, lo2;
                split_bf16(hv,  he, le);
                split_bf16(hvp, ho, lo2);
                const uint32_t wh = (uint32_t)*reinterpret_cast<unsigned short*>(&he)
                                  | ((uint32_t)*reinterpret_cast<unsigned short*>(&ho) << 16);
                const uint32_t wl = (uint32_t)*reinterpret_cast<unsigned short*>(&le)
                                  | ((uint32_t)*reinterpret_cast<unsigned short*>(&lo2) << 16);
                const uint32_t bo = (uint32_t)ch * 32768 + (uint32_t)nxt * 16384;
#pragma unroll
                for (int r = 0; r < 8; r++) {
                    ST_CLUSTER_U32(rA[r] + bo, wh);
                    ST_CLUSTER_U32(rA[r] + bo + 8192, wl);
                }
            }
            __syncthreads();
            if (tid < 8)
                MBAR_ARRIVE_REL_CLUSTER(rbar + ch * 16 + nxt * 8);
        }
    }

    out[16777216 + (size_t)bgA * 512 + (dir << 8) + ug] = hlastA;
    out[16777216 + (size_t)bgB * 512 + (dir << 8) + ug] = hlastB;

    CLUSTER_SYNC();
}

// ---------------------------------------------------------------------------
// Recurrence (cluster of 16) — same topology, half the GEMM per rank.
// 128 CTAs = 2 dirs x 4 batch-groups(16) x 16 ranks. Rank owns 16 u (64 cols);
// warp w owns 8 cols = u {2w, 2w+1} x 4 gates -> 48 HMMA + 48 LDSM per turn.
// Launched at runtime with cluster {16,1,1} (NonPortableClusterSizeAllowed).
// SMEM: Whi 32K | Wlo 32K | A[2 grp][2 buf][hi 8K|lo 8K] 64K | mask 8K | bars.
// ---------------------------------------------------------------------------
#define RQ_WHI   0
#define RQ_WLO   32768
#define RQ_A     65536
#define RQ_MASK  131072
#define RQ_BAR   139264
#define RQ_SMEM  139328

__global__ void __launch_bounds__(256, 1)
lstm_rec16_kernel(const float* __restrict__ Wr_f, const float* __restrict__ Wr_b,
                  float* __restrict__ out)
{
    extern __shared__ char smr[];
    const uint32_t sbase = smem_u32(smr);
    unsigned char* m_s = reinterpret_cast<unsigned char*>(smr + RQ_MASK);

    const int tid  = threadIdx.x;
    const int bx   = blockIdx.x;
    const int dir  = bx >> 6;                  // 0..1
    const int bgrp = (bx >> 4) & 3;            // 0..3  (16 batches each)
    const int rank = bx & 15;
    const int w    = tid >> 5, lane = tid & 31;
    const int b    = lane >> 2;
    const int q    = lane & 3;
    const int mg   = lane >> 3, lr = lane & 7;

    const int u_l  = 2 * w + (q >> 1);         // 0..15
    const int ug   = rank * 16 + u_l;          // 0..255

    // --- one-time init: Wr slice (64 cols x 256 k) -> bf16 hi/lo ----------
    const float* Wr = dir ? Wr_b : Wr_f;
    for (int i = tid; i < 16384; i += 256) {
        const int n = i & 63;                  // col = u_local*4 + gate
        const int k = i >> 6;
        const float v = __ldg(&Wr[k * 1024 + (n & 3) * 256 + rank * 16 + (n >> 2)]);
        __nv_bfloat16 hi, lo;
        split_bf16(v, hi, lo);
        const uint32_t off = swz512((uint32_t)n, (uint32_t)(k * 2));
        *reinterpret_cast<__nv_bfloat16*>(smr + RQ_WHI + off) = hi;
        *reinterpret_cast<__nv_bfloat16*>(smr + RQ_WLO + off) = lo;
    }
    for (int i = tid; i < 4096; i += 256)
        reinterpret_cast<float4*>(smr + RQ_A)[i] = make_float4(0.f, 0.f, 0.f, 0.f);
    for (int i = tid; i < 16 * 512; i += 256)
        m_s[i] = g_mask[(bgrp * 16 + (i >> 9)) * 512 + (i & 511)];
    if (tid == 0) {
        MBARRIER_INIT(sbase + RQ_BAR + 0, 16);
        MBARRIER_INIT(sbase + RQ_BAR + 8, 16);
        MBARRIER_INIT(sbase + RQ_BAR + 16, 16);
        MBARRIER_INIT(sbase + RQ_BAR + 24, 16);
    }
    __syncthreads();
    CLUSTER_SYNC();

    uint32_t rbar = 0;
    if (tid < 16) {
        rbar = mapa_rank(sbase + RQ_BAR, (uint32_t)tid);
        MBAR_ARRIVE_REL_CLUSTER(rbar);          // group 0 buf0
        MBAR_ARRIVE_REL_CLUSTER(rbar + 16);     // group 1 buf0
    }

    // Remote A-word base (lane q==0 stores pair u{2w, 2w+1} for its b).
    const uint32_t awoff = swz512((uint32_t)b, (uint32_t)(2 * (ug & ~1)));
    uint32_t rA[16];
#pragma unroll
    for (int r = 0; r < 16; r++) rA[r] = mapa_rank(sbase + RQ_A + awoff, (uint32_t)r);

    // GEMM fragment bases
    const uint32_t rowA  = (uint32_t)(lr + (mg & 1) * 8);
    const uint32_t koffA = (uint32_t)((mg >> 1) * 16);
    const uint32_t rowB  = (uint32_t)(w * 8 + lr);       // 8 n-rows per warp
    const uint32_t swA   = (uint32_t)lr << 4;
    const uint32_t baseBhi = sbase + RQ_WHI + rowB * 512;
    const uint32_t baseBlo = sbase + RQ_WLO + rowB * 512;

    const float4* Z4 = reinterpret_cast<const float4*>(g_Z);
    const int t0 = dir ? 511 : 0;

    float cst[2]   = {0.f, 0.f};
    float hprev[2] = {0.f, 0.f};
    float hlast[2] = {0.f, 0.f};
    const int bgl[2] = { bgrp * 16 + b, bgrp * 16 + b + 8 };
    float4 zn[2];
    zn[0] = __ldg(&Z4[(((size_t)dir * 512 + t0) * 64 + bgl[0]) * 256 + ug]);
    zn[1] = __ldg(&Z4[(((size_t)dir * 512 + t0) * 64 + bgl[1]) * 256 + ug]);

    for (int step = 0; step < 512; step++) {
        const int t   = dir ? (511 - step) : step;
        const int cur = step & 1;
        const int nxt = cur ^ 1;
        const uint32_t par = (uint32_t)(step >> 1) & 1u;
        const int tn = dir ? (510 - step) : (step + 1);

#pragma unroll
        for (int g = 0; g < 2; g++) {
            MBAR_WAIT_ACQ_CLUSTER(sbase + RQ_BAR + g * 16 + cur * 8, par);

            const float4 zin = zn[g];
            if (step < 511)
                zn[g] = __ldg(&Z4[(((size_t)dir * 512 + tn) * 64 + bgl[g]) * 256 + ug]);

            // ---- tensor GEMM: one n8 subtile, split-3, K=256 -------------
            const uint32_t abase = sbase + RQ_A + (uint32_t)g * 32768
                                 + (uint32_t)cur * 16384;
            const uint32_t baseAhi = abase + rowA * 512;
            const uint32_t baseAlo = baseAhi + 8192;
            float aHH[4] = {0.f, 0.f, 0.f, 0.f};
            float aHL[4] = {0.f, 0.f, 0.f, 0.f};
            float aLH[4] = {0.f, 0.f, 0.f, 0.f};
#pragma unroll
            for (int kt2 = 0; kt2 < 8; kt2++) {
                // B: one ldm4 covers 2 k-tiles (4 x 16B chunks via mg)
                const uint32_t kbB = (uint32_t)kt2 * 64 + ((uint32_t)mg << 4);
                const uint32_t offB = (kbB & 0x180u) + ((kbB & 0x70u) ^ swA)
                                    + (kbB & 0xFu);
                uint32_t bh[4], bl[4];
                ldm4(bh, baseBhi + offB);
                ldm4(bl, baseBlo + offB);
#pragma unroll
                for (int sub = 0; sub < 2; sub++) {
                    const uint32_t kbA = (uint32_t)(kt2 * 2 + sub) * 32 + koffA;
                    const uint32_t offA = (kbA & 0x180u) + ((kbA & 0x70u) ^ swA);
                    uint32_t ah[4], al[4];
                    ldm4(ah, baseAhi + offA);
                    ldm4(al, baseAlo + offA);
                    mma16816(aHH, ah, bh[sub * 2], bh[sub * 2 + 1]);
                    mma16816(aHL, ah, bl[sub * 2], bl[sub * 2 + 1]);
                    mma16816(aLH, al, bh[sub * 2], bh[sub * 2 + 1]);
                }
            }
            const float c0 = aHH[0] + aHL[0] + aLH[0];
            const float c1 = aHH[1] + aHL[1] + aLH[1];

            // ---- gate assembly: lane-pair (q xor 1) exchange -------------
            const float r0 = __shfl_xor_sync(0xffffffffu, c0, 1);
            const float r1 = __shfl_xor_sync(0xffffffffu, c1, 1);
            const bool odd = (q & 1) != 0;     // odd lanes own (c,o)
            float zi = (odd ? r0 : c0) + zin.x;
            float zf = (odd ? r1 : c1) + zin.y;
            float zc = (odd ? c0 : r0) + zin.z;
            float zo = (odd ? c1 : r1) + zin.w;

            const float gi = ftanh(zi);
            const float gf = ftanh(zf);
            const float gc = ftanh(zc);
            const float go = ftanh(zo);
            const float cn = fmaf(gf, cst[g], gi * gc);
            const float hn = go * ftanh(cn);

            const int  mrow = g * 8 + b;
            const bool mk = m_s[(mrow << 9) + t] != 0;
            const float hv = mk ? hn : hprev[g];
            cst[g]   = mk ? cn : cst[g];
            hprev[g] = hv;
            hlast[g] = hv;

            if ((q & 1) == 0)
                out[((size_t)bgl[g] * 512 + t) * 512 + (dir << 8) + ug] = hv;

            // ---- broadcast pair (u0 from q0, u1 from q2) to A[nxt] -------
            const float hvp = __shfl_xor_sync(0xffffffffu, hv, 2);
            if (q == 0) {
                __nv_bfloat16 he, le, ho, lo2;
                split_bf16(hv,  he, le);
                split_bf16(hvp, ho, lo2);
                const uint32_t wh = (uint32_t)*reinterpret_cast<unsigned short*>(&he)
                                  | ((uint32_t)*reinterpret_cast<unsigned short*>(&ho) << 16);
                const uint32_t wl = (uint32_t)*reinterpret_cast<unsigned short*>(&le)
                                  | ((uint32_t)*reinterpret_cast<unsigned short*>(&lo2) << 16);
                const uint32_t bo = (uint32_t)g * 32768 + (uint32_t)nxt * 16384;
#pragma unroll
                for (int r = 0; r < 16; r++) {
                    ST_CLUSTER_U32(rA[r] + bo, wh);
                    ST_CLUSTER_U32(rA[r] + bo + 8192, wl);
                }
            }
            __syncthreads();
            if (tid < 16)
                MBAR_ARRIVE_REL_CLUSTER(rbar + g * 16 + nxt * 8);
        }
    }

    if ((q & 1) == 0) {
        out[16777216 + (size_t)bgl[0] * 512 + (dir << 8) + ug] = hlast[0];
        out[16777216 + (size_t)bgl[1] * 512 + (dir << 8) + ug] = hlast[1];
    }

    CLUSTER_SYNC();
}

// ---------------------------------------------------------------------------
// Launch
// ---------------------------------------------------------------------------
extern "C" void kernel_launch(void* const* d_in, const int* in_sizes, int n_in,
                              void* d_out, int out_size)
{
    const float* x    = (const float*)d_in[0];
    const float* Wk_f = (const float*)d_in[1];
    const float* Wr_f = (const float*)d_in[2];
    const float* b_f  = (const float*)d_in[3];
    const float* Wk_b = (const float*)d_in[4];
    const float* Wr_b = (const float*)d_in[5];
    const float* b_b  = (const float*)d_in[6];
    float* out = (float*)d_out;

    mask_kernel<<<4096, 256>>>(x);
    convert_x_kernel<<<8192, 256>>>(x);
    convert_w_kernel<<<2048, 256>>>(Wk_f, Wk_b);

    cudaFuncSetAttribute(gemm_mma_kernel,
                         cudaFuncAttributeMaxDynamicSharedMemorySize, GEMM_SMEM_BYTES);
    dim3 gg(256, 16);
    gemm_mma_kernel<<<gg, 256, GEMM_SMEM_BYTES>>>(b_f, b_b);

    // Probe cluster-16 capability once (deterministic), else fall back to
    // the proven cluster-8 kernel.
    cudaFuncSetAttribute(lstm_rec16_kernel,
                         cudaFuncAttributeMaxDynamicSharedMemorySize, RQ_SMEM);
    cudaError_t ea = cudaFuncSetAttribute(
        lstm_rec16_kernel, cudaFuncAttributeNonPortableClusterSizeAllowed, 1);

    int maxC = 0;
    cudaLaunchConfig_t cfg = {};
    cfg.gridDim = dim3(128, 1, 1);
    cfg.blockDim = dim3(256, 1, 1);
    cfg.dynamicSmemBytes = RQ_SMEM;
    cudaLaunchAttribute attrs[1];
    attrs[0].id = cudaLaunchAttributeClusterDimension;
    attrs[0].val.clusterDim = {16, 1, 1};
    cfg.attrs = attrs;
    cfg.numAttrs = 1;
    if (ea == cudaSuccess) {
        cudaLaunchConfig_t probe = cfg;
        probe.numAttrs = 0;             // probe without fixed cluster dims
        if (cudaOccupancyMaxPotentialClusterSize(&maxC, lstm_rec16_kernel,
                                                 &probe) != cudaSuccess)
            maxC = 0;
    }

    if (maxC >= 16) {
        cudaLaunchKernelEx(&cfg, lstm_rec16_kernel, Wr_f, Wr_b, out);
    } else {
        cudaFuncSetAttribute(lstm_rec8_kernel,
                             cudaFuncAttributeMaxDynamicSharedMemorySize, RP_SMEM);
        lstm_rec8_kernel<<<64, 256, RP_SMEM>>>(Wr_f, Wr_b, out);
    }
}

// round 13
// speedup vs baseline: 3.0779x; 3.0779x over previous
#include <cuda_runtime.h>
#include <cuda_bf16.h>
#include <cstdint>
#include <cmath>

// Problem: B=64, T=512, E=256, U=256, bidirectional LSTM (all-tanh), mask carry.

// ---------------------------------------------------------------------------
// Device scratch
// ---------------------------------------------------------------------------
__device__ float g_Z[2ull * 512 * 64 * 1024];                  // [dir][t][b][u*4+g]
__device__ unsigned char g_mask[64 * 512];                     // [b][t]
__device__ __align__(16) __nv_bfloat16 g_Xhi[32768ull * 256];  // [m=t*64+b][k]
__device__ __align__(16) __nv_bfloat16 g_Xlo[32768ull * 256];
__device__ __align__(16) __nv_bfloat16 g_Whi[2ull * 1024 * 256]; // [dir][q=u*4+g][k]
__device__ __align__(16) __nv_bfloat16 g_Wlo[2ull * 1024 * 256];

// ---------------------------------------------------------------------------
// PTX helpers (family-level features only)
// ---------------------------------------------------------------------------
__device__ __forceinline__ uint32_t smem_u32(const void* p)
{
    uint32_t a;
    asm("{ .reg .u64 t; cvta.to.shared.u64 t, %1; cvt.u32.u64 %0, t; }"
        : "=r"(a) : "l"(p));
    return a;
}

#define CP_ASYNC16(dst, src) \
    asm volatile("cp.async.cg.shared.global [%0], [%1], 16;" \
                 :: "r"(dst), "l"(src) : "memory")
#define CP_ASYNC_COMMIT() asm volatile("cp.async.commit_group;" ::: "memory")
#define CP_ASYNC_WAIT(n)  asm volatile("cp.async.wait_group %0;" :: "n"(n) : "memory")

__device__ __forceinline__ void ldm4(uint32_t* r, uint32_t addr)
{
    asm volatile("ldmatrix.sync.aligned.m8n8.x4.shared.b16 {%0,%1,%2,%3}, [%4];"
                 : "=r"(r[0]), "=r"(r[1]), "=r"(r[2]), "=r"(r[3]) : "r"(addr));
}

__device__ __forceinline__ void mma16816(float* c, const uint32_t* a,
                                         uint32_t b0, uint32_t b1)
{
    asm volatile(
        "mma.sync.aligned.m16n8k16.row.col.f32.bf16.bf16.f32 "
        "{%0,%1,%2,%3}, {%4,%5,%6,%7}, {%8,%9}, {%0,%1,%2,%3};"
        : "+f"(c[0]), "+f"(c[1]), "+f"(c[2]), "+f"(c[3])
        : "r"(a[0]), "r"(a[1]), "r"(a[2]), "r"(a[3]), "r"(b0), "r"(b1));
}

__device__ __forceinline__ uint32_t mapa_rank(uint32_t addr, uint32_t rank)
{
    uint32_t r;
    asm("mapa.shared::cluster.u32 %0, %1, %2;" : "=r"(r) : "r"(addr), "r"(rank));
    return r;
}
#define ST_CLUSTER_U128(addr, v) \
    asm volatile("st.shared::cluster.v4.b32 [%0], {%1, %2, %3, %4};" \
                 :: "r"(addr), "r"((v).x), "r"((v).y), "r"((v).z), "r"((v).w) \
                 : "memory")

#define MBARRIER_INIT(addr, count) \
    asm volatile("mbarrier.init.shared.b64 [%0], %1;" \
                 :: "r"((uint32_t)(addr)), "r"((uint32_t)(count)) : "memory")
#define MBAR_ARRIVE_REL_CLUSTER(addr) \
    asm volatile("mbarrier.arrive.release.cluster.shared::cluster.b64 _, [%0];" \
                 :: "r"((uint32_t)(addr)) : "memory")

#define MBAR_WAIT_ACQ_CLUSTER(mbar, parity) do { \
    uint32_t _m = (uint32_t)(mbar); \
    uint32_t _p = (uint32_t)(parity); \
    uint32_t _done; \
    asm volatile( \
        "{\n\t.reg .pred p;\n\t" \
        "mbarrier.try_wait.parity.acquire.cluster.shared::cta.b64 p, [%1], %2;\n\t" \
        "selp.b32 %0, 1, 0, p;\n\t}" \
        : "=r"(_done) : "r"(_m), "r"(_p) : "memory"); \
    if (!_done) { \
        asm volatile( \
            "{\n\t.reg .pred P1;\n\t" \
            "WL_%=:\n\t" \
            "mbarrier.try_wait.parity.acquire.cluster.shared::cta.b64 P1, [%0], %1, 0x989680;\n\t" \
            "@P1 bra.uni WD_%=;\n\t" \
            "bra.uni WL_%=;\n\t" \
            "WD_%=:\n\t}" \
            :: "r"(_m), "r"(_p) : "memory"); \
    } \
} while (0)

#define CLUSTER_SYNC() do { \
    asm volatile("barrier.cluster.arrive.aligned;" ::: "memory"); \
    asm volatile("barrier.cluster.wait.aligned;"   ::: "memory"); \
} while (0)

// Fast tanh: 1 - 2/(e^{2x}+1)  (MUFU path; rel err ~1e-6, exact saturation).
__device__ __forceinline__ float ftanh(float x)
{
    float e = __expf(2.f * x);
    return 1.f - __fdividef(2.f, e + 1.f);
}

__device__ __forceinline__ uint32_t swz512(uint32_t row, uint32_t kb)
{
    return row * 512 + (kb & 0x180u) + ((kb & 0x70u) ^ ((row & 7u) << 4)) + (kb & 0xFu);
}

// ---------------------------------------------------------------------------
// Mask kernel: mask[b][t] = any(x[b,t,:] != 0)
// ---------------------------------------------------------------------------
__global__ void mask_kernel(const float* __restrict__ x)
{
    int gw   = (blockIdx.x * blockDim.x + threadIdx.x) >> 5;
    int lane = threadIdx.x & 31;
    if (gw >= 64 * 512) return;
    const float4* p = reinterpret_cast<const float4*>(x + (size_t)gw * 256);
    float4 a = p[lane];
    float4 b = p[lane + 32];
    bool nz = (a.x != 0.f) || (a.y != 0.f) || (a.z != 0.f) || (a.w != 0.f) ||
              (b.x != 0.f) || (b.y != 0.f) || (b.z != 0.f) || (b.w != 0.f);
    unsigned m = __ballot_sync(0xffffffffu, nz);
    if (lane == 0) g_mask[gw] = (m != 0u) ? 1 : 0;
}

// ---------------------------------------------------------------------------
// Converters: fp32 -> (hi, lo) bf16 split
// ---------------------------------------------------------------------------
__device__ __forceinline__ void split_bf16(float f, __nv_bfloat16& hi, __nv_bfloat16& lo)
{
    hi = __float2bfloat16_rn(f);
    lo = __float2bfloat16_rn(f - __bfloat162float(hi));
}

__global__ __launch_bounds__(256) void convert_x_kernel(const float* __restrict__ x)
{
    uint32_t idx = blockIdx.x * 256u + threadIdx.x;   // 2,097,152 total
    int m = idx >> 6, q = idx & 63;
    int b = m & 63, t = m >> 6;
    float4 v = *reinterpret_cast<const float4*>(x + ((size_t)b * 512 + t) * 256 + q * 4);
    __nv_bfloat16 h0, h1, h2, h3, l0, l1, l2, l3;
    split_bf16(v.x, h0, l0);
    split_bf16(v.y, h1, l1);
    split_bf16(v.z, h2, l2);
    split_bf16(v.w, h3, l3);
    __nv_bfloat162 hp0(h0, h1), hp1(h2, h3), lp0(l0, l1), lp1(l2, l3);
    uint2 hv, lv;
    hv.x = *reinterpret_cast<uint32_t*>(&hp0);
    hv.y = *reinterpret_cast<uint32_t*>(&hp1);
    lv.x = *reinterpret_cast<uint32_t*>(&lp0);
    lv.y = *reinterpret_cast<uint32_t*>(&lp1);
    *reinterpret_cast<uint2*>(g_Xhi + (size_t)m * 256 + q * 4) = hv;
    *reinterpret_cast<uint2*>(g_Xlo + (size_t)m * 256 + q * 4) = lv;
}

__global__ __launch_bounds__(256) void convert_w_kernel(
    const float* __restrict__ Wk_f, const float* __restrict__ Wk_b)
{
    uint32_t idx = blockIdx.x * 256u + threadIdx.x;   // 524,288 total
    int dir = idx >> 18;
    uint32_t rem = idx & 0x3FFFFu;
    int q = rem >> 8, k = rem & 255;
    int u = q >> 2, g = q & 3;
    float v = (dir ? Wk_b : Wk_f)[k * 1024 + g * 256 + u];
    __nv_bfloat16 hi, lo;
    split_bf16(v, hi, lo);
    g_Whi[idx] = hi;
    g_Wlo[idx] = lo;
}

// ---------------------------------------------------------------------------
// Input GEMM via mma.sync bf16 split-3 (proven: ~255us, tensor 67%)
// ---------------------------------------------------------------------------
#define GEMM_STAGE_BYTES 65536
#define GEMM_SMEM_BYTES  (2 * GEMM_STAGE_BYTES + 1024)

__global__ __launch_bounds__(256, 1) void gemm_mma_kernel(
    const float* __restrict__ b_f, const float* __restrict__ b_b)
{
    extern __shared__ char smc[];
    char* stages = smc;
    float* bias_s = reinterpret_cast<float*>(smc + 2 * GEMM_STAGE_BYTES);
    const uint32_t st_u32 = smem_u32(stages);

    const int tid  = threadIdx.x;
    const int wid  = tid >> 5, lane = tid & 31;
    const int wm   = wid & 3, wn = wid >> 2;
    const int mt   = blockIdx.x * 128;
    const int nt   = blockIdx.y;
    const int dir  = nt >> 3;
    const int q0   = (nt & 7) * 128;

    if (tid < 128) {
        const int q = q0 + tid;
        bias_s[tid] = (dir ? b_b : b_f)[(q & 3) * 256 + (q >> 2)];
    }

    const char* srcs[4] = {
        reinterpret_cast<const char*>(g_Xhi),
        reinterpret_cast<const char*>(g_Xlo),
        reinterpret_cast<const char*>(g_Whi),
        reinterpret_cast<const char*>(g_Wlo)
    };

    auto load_chunk = [&](int c, int s) {
        const uint32_t sb = st_u32 + (uint32_t)s * GEMM_STAGE_BYTES;
        const int koff = c * 128;
#pragma unroll
        for (int it = 0; it < 16; it++) {
            const int idx    = it * 256 + tid;
            const int region = idx >> 10;
            const int r      = (idx >> 3) & 127;
            const int q4     = idx & 7;
            const int grow   = (region < 2) ? (mt + r) : (dir * 1024 + q0 + r);
            const char* src  = srcs[region] + (size_t)grow * 512 + koff + q4 * 16;
            const uint32_t dst = sb + region * 16384 + r * 128
                               + (((uint32_t)q4 * 16) ^ (((uint32_t)(r & 7)) * 16));
            CP_ASYNC16(dst, src);
        }
    };

    const int grp = lane >> 3, lr = lane & 7;
    const uint32_t xr16 = (uint32_t)lr * 16;
    const uint32_t koffA = (uint32_t)(grp >> 1) * 16;
    const uint32_t koffB = (uint32_t)(grp & 1) * 16;
    uint32_t baseA[2], baseB[4];
#pragma unroll
    for (int i = 0; i < 2; i++) {
        const int rowA = wm * 32 + i * 16 + lr + (grp & 1) * 8;
        baseA[i] = (uint32_t)rowA * 128;
    }
#pragma unroll
    for (int j2 = 0; j2 < 4; j2++) {
        const int rowB = wn * 64 + j2 * 16 + lr + (grp >> 1) * 8;
        baseB[j2] = (uint32_t)rowB * 128;
    }

    float acc[2][8][4];
#pragma unroll
    for (int i = 0; i < 2; i++)
#pragma unroll
        for (int j = 0; j < 8; j++)
#pragma unroll
            for (int v = 0; v < 4; v++) acc[i][j][v] = 0.f;

    load_chunk(0, 0);
    CP_ASYNC_COMMIT();

#pragma unroll
    for (int c = 0; c < 4; c++) {
        if (c < 3) { load_chunk(c + 1, (c + 1) & 1); CP_ASYNC_COMMIT(); }
        if (c < 3) CP_ASYNC_WAIT(1); else CP_ASYNC_WAIT(0);
        __syncthreads();

        const uint32_t sb = st_u32 + (uint32_t)(c & 1) * GEMM_STAGE_BYTES;
        const uint32_t Ah = sb, Al = sb + 16384, Bh = sb + 32768, Bl = sb + 49152;

#pragma unroll
        for (int ks = 0; ks < 4; ks++) {
            const uint32_t offA = (((uint32_t)ks * 32) + koffA) ^ xr16;
            const uint32_t offB = (((uint32_t)ks * 32) + koffB) ^ xr16;
            uint32_t ah[2][4], al[2][4], bh[4][4], bl[4][4];
#pragma unroll
            for (int i = 0; i < 2; i++) {
                ldm4(ah[i], Ah + baseA[i] + offA);
                ldm4(al[i], Al + baseA[i] + offA);
            }
#pragma unroll
            for (int j2 = 0; j2 < 4; j2++) {
                ldm4(bh[j2], Bh + baseB[j2] + offB);
                ldm4(bl[j2], Bl + baseB[j2] + offB);
            }
#pragma unroll
            for (int i = 0; i < 2; i++)
#pragma unroll
                for (int j = 0; j < 8; j++) {
                    const int j2 = j >> 1, sel = (j & 1) * 2;
                    mma16816(acc[i][j], ah[i], bh[j2][sel], bh[j2][sel + 1]);
                    mma16816(acc[i][j], ah[i], bl[j2][sel], bl[j2][sel + 1]);
                    mma16816(acc[i][j], al[i], bh[j2][sel], bh[j2][sel + 1]);
                }
        }
        __syncthreads();
    }

    const int mrow0 = mt + wm * 32 + (lane >> 2);
    const int qcol0 = q0 + wn * 64 + (lane & 3) * 2;
#pragma unroll
    for (int i = 0; i < 2; i++) {
#pragma unroll
        for (int j = 0; j < 8; j++) {
            const int q  = qcol0 + j * 8;
            const float bx = bias_s[q - q0], by = bias_s[q - q0 + 1];
#pragma unroll
            for (int half = 0; half < 2; half++) {
                const int m  = mrow0 + i * 16 + half * 8;
                const int bb = m & 63, tt = m >> 6;
                float2 v;
                v.x = acc[i][j][half * 2 + 0] + bx;
                v.y = acc[i][j][half * 2 + 1] + by;
                *reinterpret_cast<float2*>(
                    g_Z + (((size_t)dir * 512 + tt) * 64 + bb) * 1024 + q) = v;
            }
        }
    }
}

// ---------------------------------------------------------------------------
// Recurrence — R10 structure (64 CTAs = 2 dirs x 4 bgroups(16) x 8 ranks,
// 2 interleaved 8-batch chains, mbarrier ring) with ONE change: the per-turn
// h broadcast is staged into SMEM and copied to the 8 remote A tiles with
// ST.128 (512 wide stores/turn instead of 2048 scalar remote stores).
// SMEM: Whi 64K | Wlo 64K | A[2 ch][2 buf][hi 8K|lo 8K] 64K | mask 8K | bars
//       | stage 1K.
// ---------------------------------------------------------------------------
#define RP_WHI    0
#define RP_WLO    65536
#define RP_A      131072
#define RP_MASK   196608
#define RP_BAR    204800
#define RP_STAGE  204864
#define RP_SMEM   205888

__global__ void __cluster_dims__(8, 1, 1) __launch_bounds__(256, 1)
lstm_rec_kernel(const float* __restrict__ Wr_f, const float* __restrict__ Wr_b,
                float* __restrict__ out)
{
    extern __shared__ char smr[];
    const uint32_t sbase = smem_u32(smr);
    unsigned char* m_s = reinterpret_cast<unsigned char*>(smr + RP_MASK);

    const int tid  = threadIdx.x;
    const int bx   = blockIdx.x;
    const int dir  = bx >> 5;
    const int bgrp = (bx >> 3) & 3;
    const int rank = bx & 7;
    const int w    = tid >> 5, lane = tid & 31;
    const int b    = lane >> 2;
    const int q    = lane & 3;
    const int mg   = lane >> 3, lr = lane & 7;

    const int u_l  = 4 * w + (q >> 1) + 2 * (q & 1);
    const int ug   = (rank << 5) + u_l;

    const float* Wr = dir ? Wr_b : Wr_f;
    for (int i = tid; i < 32768; i += 256) {
        const int n = i & 127;
        const int k = i >> 7;
        const float v = __ldg(&Wr[k * 1024 + (n & 3) * 256 + (rank << 5) + (n >> 2)]);
        __nv_bfloat16 hi, lo;
        split_bf16(v, hi, lo);
        const uint32_t off = swz512((uint32_t)n, (uint32_t)(k * 2));
        *reinterpret_cast<__nv_bfloat16*>(smr + RP_WHI + off) = hi;
        *reinterpret_cast<__nv_bfloat16*>(smr + RP_WLO + off) = lo;
    }
    for (int i = tid; i < 4096; i += 256)
        reinterpret_cast<float4*>(smr + RP_A)[i] = make_float4(0.f, 0.f, 0.f, 0.f);
    for (int i = tid; i < 16 * 512; i += 256)
        m_s[i] = g_mask[(bgrp * 16 + (i >> 9)) * 512 + (i & 511)];
    if (tid == 0) {
        MBARRIER_INIT(sbase + RP_BAR + 0, 8);
        MBARRIER_INIT(sbase + RP_BAR + 8, 8);
        MBARRIER_INIT(sbase + RP_BAR + 16, 8);
        MBARRIER_INIT(sbase + RP_BAR + 24, 8);
    }
    __syncthreads();
    CLUSTER_SYNC();

    uint32_t rbar = 0;
    if (tid < 8) {
        rbar = mapa_rank(sbase + RP_BAR, (uint32_t)tid);
        MBAR_ARRIVE_REL_CLUSTER(rbar);
        MBAR_ARRIVE_REL_CLUSTER(rbar + 16);
    }

    // Staged-broadcast copy mapping: warp (tid>>5) copies the stage to remote
    // rank (tid>>5); lane idx covers 32 chunks (8 rows x 4 chunks) per part.
    // Chunk (b2, j) holds u [32*rank + 8j, +8) of row b2 — 16 bytes, swizzle-
    // invariant as a block.
    const int cp_rank = tid >> 5;
    const int cp_idx  = tid & 31;
    const int cp_b    = cp_idx >> 2;
    const int cp_j    = cp_idx & 3;
    const uint32_t cp_swz = swz512((uint32_t)cp_b,
                                   (uint32_t)(rank * 64 + cp_j * 16));
    const uint32_t cp_dst = mapa_rank(sbase + RP_A, (uint32_t)cp_rank) + cp_swz;
    const uint32_t cp_src = sbase + RP_STAGE + (uint32_t)cp_idx * 16;
    // Gate-thread stage word address: word index b*16 + 2w + q (q<2 lanes).
    const uint32_t st_word = sbase + RP_STAGE + ((uint32_t)(b * 16 + 2 * w + q) << 2);

    const uint32_t rowA  = (uint32_t)(lr + (mg & 1) * 8);
    const uint32_t koffA = (uint32_t)((mg >> 1) * 16);
    const uint32_t rowB  = (uint32_t)(w * 16 + lr + (mg >> 1) * 8);
    const uint32_t koffB = (uint32_t)((mg & 1) * 16);
    const uint32_t swA   = (uint32_t)lr << 4;
    const uint32_t baseBhi = sbase + RP_WHI + rowB * 512;
    const uint32_t baseBlo = sbase + RP_WLO + rowB * 512;

    const float4* Z4 = reinterpret_cast<const float4*>(g_Z);
    const int t0 = dir ? 511 : 0;

    float cstA = 0.f, hprevA = 0.f, hlastA = 0.f;
    float cstB = 0.f, hprevB = 0.f, hlastB = 0.f;
    const int bgA = bgrp * 16 + b;
    const int bgB = bgA + 8;
    float4 znA = __ldg(&Z4[(((size_t)dir * 512 + t0) * 64 + bgA) * 256 + ug]);
    float4 znB = __ldg(&Z4[(((size_t)dir * 512 + t0) * 64 + bgB) * 256 + ug]);

    for (int step = 0; step < 512; step++) {
        const int t   = dir ? (511 - step) : step;
        const int cur = step & 1;
        const int nxt = cur ^ 1;
        const uint32_t par = (uint32_t)(step >> 1) & 1u;
        const int tn = dir ? (510 - step) : (step + 1);

#pragma unroll
        for (int ch = 0; ch < 2; ch++) {
            MBAR_WAIT_ACQ_CLUSTER(sbase + RP_BAR + ch * 16 + cur * 8, par);

            float4 zin = ch ? znB : znA;
            if (step < 511) {
                const int bgl = ch ? bgB : bgA;
                float4 z = __ldg(&Z4[(((size_t)dir * 512 + tn) * 64 + bgl) * 256 + ug]);
                if (ch) znB = z; else znA = z;
            }

            const uint32_t abase = sbase + RP_A + (uint32_t)ch * 32768
                                 + (uint32_t)cur * 16384;
            const uint32_t baseAhi = abase + rowA * 512;
            const uint32_t baseAlo = baseAhi + 8192;
            float a0[4] = {0.f, 0.f, 0.f, 0.f};
            float b0[4] = {0.f, 0.f, 0.f, 0.f};
            float c0v[4] = {0.f, 0.f, 0.f, 0.f};
            float a1[4] = {0.f, 0.f, 0.f, 0.f};
            float b1[4] = {0.f, 0.f, 0.f, 0.f};
            float c1v[4] = {0.f, 0.f, 0.f, 0.f};
#pragma unroll
            for (int kt = 0; kt < 16; kt++) {
                const uint32_t kbA = (uint32_t)kt * 32 + koffA;
                const uint32_t kbB = (uint32_t)kt * 32 + koffB;
                const uint32_t offA = (kbA & 0x180u) + ((kbA & 0x70u) ^ swA);
                const uint32_t offB = (kbB & 0x180u) + ((kbB & 0x70u) ^ swA);
                uint32_t ah[4], al[4], bh[4], bl[4];
                ldm4(ah, baseAhi + offA);
                ldm4(al, baseAlo + offA);
                ldm4(bh, baseBhi + offB);
                ldm4(bl, baseBlo + offB);
                mma16816(a0, ah, bh[0], bh[1]);
                mma16816(b0, ah, bl[0], bl[1]);
                mma16816(c0v, al, bh[0], bh[1]);
                mma16816(a1, ah, bh[2], bh[3]);
                mma16816(b1, ah, bl[2], bl[3]);
                mma16816(c1v, al, bh[2], bh[3]);
            }
            const float c0 = a0[0] + b0[0] + c0v[0];
            const float c1 = a0[1] + b0[1] + c0v[1];
            const float d0 = a1[0] + b1[0] + c1v[0];
            const float d1 = a1[1] + b1[1] + c1v[1];

            const bool odd = (q & 1) != 0;
            const float s0 = odd ? c0 : d0;
            const float s1 = odd ? c1 : d1;
            const float r0 = __shfl_xor_sync(0xffffffffu, s0, 1);
            const float r1 = __shfl_xor_sync(0xffffffffu, s1, 1);
            float zi = (odd ? r0 : c0) + zin.x;
            float zf = (odd ? r1 : c1) + zin.y;
            float zc = (odd ? d0 : r0) + zin.z;
            float zo = (odd ? d1 : r1) + zin.w;

            const float gi = ftanh(zi);
            const float gf = ftanh(zf);
            const float gc = ftanh(zc);
            const float go = ftanh(zo);
            const float cstp = ch ? cstB : cstA;
            const float hpp  = ch ? hprevB : hprevA;
            const float cn = fmaf(gf, cstp, gi * gc);
            const float hn = go * ftanh(cn);

            const int  mrow = ch ? (b + 8) : b;
            const bool mk = m_s[(mrow << 9) + t] != 0;
            const float hv = mk ? hn : hpp;
            const float cv = mk ? cn : cstp;
            if (ch) { cstB = cv; hprevB = hv; hlastB = hv; }
            else    { cstA = cv; hprevA = hv; hlastA = hv; }

            const int bgl = ch ? bgB : bgA;
            out[((size_t)bgl * 512 + t) * 512 + (dir << 8) + ug] = hv;

            // ---- stage packed bf16 hi/lo words locally ------------------
            const float hvp = __shfl_xor_sync(0xffffffffu, hv, 2);
            if (q < 2) {
                __nv_bfloat16 he, le, ho, lo2;
                split_bf16(hv,  he, le);
                split_bf16(hvp, ho, lo2);
                const uint32_t wh = (uint32_t)*reinterpret_cast<unsigned short*>(&he)
                                  | ((uint32_t)*reinterpret_cast<unsigned short*>(&ho) << 16);
                const uint32_t wl = (uint32_t)*reinterpret_cast<unsigned short*>(&le)
                                  | ((uint32_t)*reinterpret_cast<unsigned short*>(&lo2) << 16);
                asm volatile("st.shared.u32 [%0], %1;" :: "r"(st_word), "r"(wh) : "memory");
                asm volatile("st.shared.u32 [%0], %1;" :: "r"(st_word + 512), "r"(wl) : "memory");
            }
            __syncthreads();           // stage complete

            // ---- wide remote copy: warp cp_rank -> remote rank cp_rank ---
            {
                const uint32_t bo = (uint32_t)ch * 32768 + (uint32_t)nxt * 16384;
                uint4 vh, vl;
                asm volatile("ld.shared.v4.b32 {%0,%1,%2,%3}, [%4];"
                             : "=r"(vh.x), "=r"(vh.y), "=r"(vh.z), "=r"(vh.w)
                             : "r"(cp_src));
                asm volatile("ld.shared.v4.b32 {%0,%1,%2,%3}, [%4];"
                             : "=r"(vl.x), "=r"(vl.y), "=r"(vl.z), "=r"(vl.w)
                             : "r"(cp_src + 512));
                ST_CLUSTER_U128(cp_dst + bo, vh);
                ST_CLUSTER_U128(cp_dst + bo + 8192, vl);
            }
            __syncthreads();           // all remote stores issued
            if (tid < 8)
                MBAR_ARRIVE_REL_CLUSTER(rbar + ch * 16 + nxt * 8);
        }
    }

    out[16777216 + (size_t)bgA * 512 + (dir << 8) + ug] = hlastA;
    out[16777216 + (size_t)bgB * 512 + (dir << 8) + ug] = hlastB;

    CLUSTER_SYNC();
}

// ---------------------------------------------------------------------------
// Launch
// ---------------------------------------------------------------------------
extern "C" void kernel_launch(void* const* d_in, const int* in_sizes, int n_in,
                              void* d_out, int out_size)
{
    const float* x    = (const float*)d_in[0];
    const float* Wk_f = (const float*)d_in[1];
    const float* Wr_f = (const float*)d_in[2];
    const float* b_f  = (const float*)d_in[3];
    const float* Wk_b = (const float*)d_in[4];
    const float* Wr_b = (const float*)d_in[5];
    const float* b_b  = (const float*)d_in[6];
    float* out = (float*)d_out;

    mask_kernel<<<4096, 256>>>(x);
    convert_x_kernel<<<8192, 256>>>(x);
    convert_w_kernel<<<2048, 256>>>(Wk_f, Wk_b);

    cudaFuncSetAttribute(gemm_mma_kernel,
                         cudaFuncAttributeMaxDynamicSharedMemorySize, GEMM_SMEM_BYTES);
    dim3 gg(256, 16);
    gemm_mma_kernel<<<gg, 256, GEMM_SMEM_BYTES>>>(b_f, b_b);

    cudaFuncSetAttribute(lstm_rec_kernel,
                         cudaFuncAttributeMaxDynamicSharedMemorySize, RP_SMEM);
    lstm_rec_kernel<<<64, 256, RP_SMEM>>>(Wr_f, Wr_b, out);
}

// round 14
// speedup vs baseline: 3.2001x; 1.0397x over previous
#include <cuda_runtime.h>
#include <cuda_bf16.h>
#include <cstdint>
#include <cmath>

// Problem: B=64, T=512, E=256, U=256, bidirectional LSTM (all-tanh), mask carry.

// ---------------------------------------------------------------------------
// Device scratch
// ---------------------------------------------------------------------------
__device__ float g_Z[2ull * 512 * 64 * 1024];                  // [dir][t][b][u*4+g]
__device__ unsigned char g_mask[64 * 512];                     // [b][t]
__device__ __align__(16) __nv_bfloat16 g_Xhi[32768ull * 256];  // [m=t*64+b][k]
__device__ __align__(16) __nv_bfloat16 g_Xlo[32768ull * 256];
__device__ __align__(16) __nv_bfloat16 g_Whi[2ull * 1024 * 256]; // [dir][q=u*4+g][k]
__device__ __align__(16) __nv_bfloat16 g_Wlo[2ull * 1024 * 256];

// ---------------------------------------------------------------------------
// PTX helpers (family-level features only)
// ---------------------------------------------------------------------------
__device__ __forceinline__ uint32_t smem_u32(const void* p)
{
    uint32_t a;
    asm("{ .reg .u64 t; cvta.to.shared.u64 t, %1; cvt.u32.u64 %0, t; }"
        : "=r"(a) : "l"(p));
    return a;
}

#define CP_ASYNC16(dst, src) \
    asm volatile("cp.async.cg.shared.global [%0], [%1], 16;" \
                 :: "r"(dst), "l"(src) : "memory")
#define CP_ASYNC_COMMIT() asm volatile("cp.async.commit_group;" ::: "memory")
#define CP_ASYNC_WAIT(n)  asm volatile("cp.async.wait_group %0;" :: "n"(n) : "memory")

__device__ __forceinline__ void ldm4(uint32_t* r, uint32_t addr)
{
    asm volatile("ldmatrix.sync.aligned.m8n8.x4.shared.b16 {%0,%1,%2,%3}, [%4];"
                 : "=r"(r[0]), "=r"(r[1]), "=r"(r[2]), "=r"(r[3]) : "r"(addr));
}

__device__ __forceinline__ void mma16816(float* c, const uint32_t* a,
                                         uint32_t b0, uint32_t b1)
{
    asm volatile(
        "mma.sync.aligned.m16n8k16.row.col.f32.bf16.bf16.f32 "
        "{%0,%1,%2,%3}, {%4,%5,%6,%7}, {%8,%9}, {%0,%1,%2,%3};"
        : "+f"(c[0]), "+f"(c[1]), "+f"(c[2]), "+f"(c[3])
        : "r"(a[0]), "r"(a[1]), "r"(a[2]), "r"(a[3]), "r"(b0), "r"(b1));
}

__device__ __forceinline__ uint32_t mapa_rank(uint32_t addr, uint32_t rank)
{
    uint32_t r;
    asm("mapa.shared::cluster.u32 %0, %1, %2;" : "=r"(r) : "r"(addr), "r"(rank));
    return r;
}
#define ST_CLUSTER_U128(addr, v) \
    asm volatile("st.shared::cluster.v4.b32 [%0], {%1, %2, %3, %4};" \
                 :: "r"(addr), "r"((v).x), "r"((v).y), "r"((v).z), "r"((v).w) \
                 : "memory")

#define MBARRIER_INIT(addr, count) \
    asm volatile("mbarrier.init.shared.b64 [%0], %1;" \
                 :: "r"((uint32_t)(addr)), "r"((uint32_t)(count)) : "memory")
#define MBAR_ARRIVE_REL_CLUSTER(addr) \
    asm volatile("mbarrier.arrive.release.cluster.shared::cluster.b64 _, [%0];" \
                 :: "r"((uint32_t)(addr)) : "memory")

#define MBAR_WAIT_ACQ_CLUSTER(mbar, parity) do { \
    uint32_t _m = (uint32_t)(mbar); \
    uint32_t _p = (uint32_t)(parity); \
    uint32_t _done; \
    asm volatile( \
        "{\n\t.reg .pred p;\n\t" \
        "mbarrier.try_wait.parity.acquire.cluster.shared::cta.b64 p, [%1], %2;\n\t" \
        "selp.b32 %0, 1, 0, p;\n\t}" \
        : "=r"(_done) : "r"(_m), "r"(_p) : "memory"); \
    if (!_done) { \
        asm volatile( \
            "{\n\t.reg .pred P1;\n\t" \
            "WL_%=:\n\t" \
            "mbarrier.try_wait.parity.acquire.cluster.shared::cta.b64 P1, [%0], %1, 0x989680;\n\t" \
            "@P1 bra.uni WD_%=;\n\t" \
            "bra.uni WL_%=;\n\t" \
            "WD_%=:\n\t}" \
            :: "r"(_m), "r"(_p) : "memory"); \
    } \
} while (0)

#define CLUSTER_SYNC() do { \
    asm volatile("barrier.cluster.arrive.aligned;" ::: "memory"); \
    asm volatile("barrier.cluster.wait.aligned;"   ::: "memory"); \
} while (0)

#define NAMED_BAR(id, cnt) \
    asm volatile("bar.sync %0, %1;" :: "r"(id), "r"(cnt) : "memory")

// Fast tanh: 1 - 2/(e^{2x}+1)  (MUFU path; rel err ~1e-6, exact saturation).
__device__ __forceinline__ float ftanh(float x)
{
    float e = __expf(2.f * x);
    return 1.f - __fdividef(2.f, e + 1.f);
}

__device__ __forceinline__ uint32_t swz512(uint32_t row, uint32_t kb)
{
    return row * 512 + (kb & 0x180u) + ((kb & 0x70u) ^ ((row & 7u) << 4)) + (kb & 0xFu);
}

// ---------------------------------------------------------------------------
// Mask kernel: mask[b][t] = any(x[b,t,:] != 0)
// ---------------------------------------------------------------------------
__global__ void mask_kernel(const float* __restrict__ x)
{
    int gw   = (blockIdx.x * blockDim.x + threadIdx.x) >> 5;
    int lane = threadIdx.x & 31;
    if (gw >= 64 * 512) return;
    const float4* p = reinterpret_cast<const float4*>(x + (size_t)gw * 256);
    float4 a = p[lane];
    float4 b = p[lane + 32];
    bool nz = (a.x != 0.f) || (a.y != 0.f) || (a.z != 0.f) || (a.w != 0.f) ||
              (b.x != 0.f) || (b.y != 0.f) || (b.z != 0.f) || (b.w != 0.f);
    unsigned m = __ballot_sync(0xffffffffu, nz);
    if (lane == 0) g_mask[gw] = (m != 0u) ? 1 : 0;
}

// ---------------------------------------------------------------------------
// Converters: fp32 -> (hi, lo) bf16 split
// ---------------------------------------------------------------------------
__device__ __forceinline__ void split_bf16(float f, __nv_bfloat16& hi, __nv_bfloat16& lo)
{
    hi = __float2bfloat16_rn(f);
    lo = __float2bfloat16_rn(f - __bfloat162float(hi));
}

__global__ __launch_bounds__(256) void convert_x_kernel(const float* __restrict__ x)
{
    uint32_t idx = blockIdx.x * 256u + threadIdx.x;   // 2,097,152 total
    int m = idx >> 6, q = idx & 63;
    int b = m & 63, t = m >> 6;
    float4 v = *reinterpret_cast<const float4*>(x + ((size_t)b * 512 + t) * 256 + q * 4);
    __nv_bfloat16 h0, h1, h2, h3, l0, l1, l2, l3;
    split_bf16(v.x, h0, l0);
    split_bf16(v.y, h1, l1);
    split_bf16(v.z, h2, l2);
    split_bf16(v.w, h3, l3);
    __nv_bfloat162 hp0(h0, h1), hp1(h2, h3), lp0(l0, l1), lp1(l2, l3);
    uint2 hv, lv;
    hv.x = *reinterpret_cast<uint32_t*>(&hp0);
    hv.y = *reinterpret_cast<uint32_t*>(&hp1);
    lv.x = *reinterpret_cast<uint32_t*>(&lp0);
    lv.y = *reinterpret_cast<uint32_t*>(&lp1);
    *reinterpret_cast<uint2*>(g_Xhi + (size_t)m * 256 + q * 4) = hv;
    *reinterpret_cast<uint2*>(g_Xlo + (size_t)m * 256 + q * 4) = lv;
}

__global__ __launch_bounds__(256) void convert_w_kernel(
    const float* __restrict__ Wk_f, const float* __restrict__ Wk_b)
{
    uint32_t idx = blockIdx.x * 256u + threadIdx.x;   // 524,288 total
    int dir = idx >> 18;
    uint32_t rem = idx & 0x3FFFFu;
    int q = rem >> 8, k = rem & 255;
    int u = q >> 2, g = q & 3;
    float v = (dir ? Wk_b : Wk_f)[k * 1024 + g * 256 + u];
    __nv_bfloat16 hi, lo;
    split_bf16(v, hi, lo);
    g_Whi[idx] = hi;
    g_Wlo[idx] = lo;
}

// ---------------------------------------------------------------------------
// Input GEMM via mma.sync bf16 split-3 (proven: ~255us, tensor 67%)
// ---------------------------------------------------------------------------
#define GEMM_STAGE_BYTES 65536
#define GEMM_SMEM_BYTES  (2 * GEMM_STAGE_BYTES + 1024)

__global__ __launch_bounds__(256, 1) void gemm_mma_kernel(
    const float* __restrict__ b_f, const float* __restrict__ b_b)
{
    extern __shared__ char smc[];
    char* stages = smc;
    float* bias_s = reinterpret_cast<float*>(smc + 2 * GEMM_STAGE_BYTES);
    const uint32_t st_u32 = smem_u32(stages);

    const int tid  = threadIdx.x;
    const int wid  = tid >> 5, lane = tid & 31;
    const int wm   = wid & 3, wn = wid >> 2;
    const int mt   = blockIdx.x * 128;
    const int nt   = blockIdx.y;
    const int dir  = nt >> 3;
    const int q0   = (nt & 7) * 128;

    if (tid < 128) {
        const int q = q0 + tid;
        bias_s[tid] = (dir ? b_b : b_f)[(q & 3) * 256 + (q >> 2)];
    }

    const char* srcs[4] = {
        reinterpret_cast<const char*>(g_Xhi),
        reinterpret_cast<const char*>(g_Xlo),
        reinterpret_cast<const char*>(g_Whi),
        reinterpret_cast<const char*>(g_Wlo)
    };

    auto load_chunk = [&](int c, int s) {
        const uint32_t sb = st_u32 + (uint32_t)s * GEMM_STAGE_BYTES;
        const int koff = c * 128;
#pragma unroll
        for (int it = 0; it < 16; it++) {
            const int idx    = it * 256 + tid;
            const int region = idx >> 10;
            const int r      = (idx >> 3) & 127;
            const int q4     = idx & 7;
            const int grow   = (region < 2) ? (mt + r) : (dir * 1024 + q0 + r);
            const char* src  = srcs[region] + (size_t)grow * 512 + koff + q4 * 16;
            const uint32_t dst = sb + region * 16384 + r * 128
                               + (((uint32_t)q4 * 16) ^ (((uint32_t)(r & 7)) * 16));
            CP_ASYNC16(dst, src);
        }
    };

    const int grp = lane >> 3, lr = lane & 7;
    const uint32_t xr16 = (uint32_t)lr * 16;
    const uint32_t koffA = (uint32_t)(grp >> 1) * 16;
    const uint32_t koffB = (uint32_t)(grp & 1) * 16;
    uint32_t baseA[2], baseB[4];
#pragma unroll
    for (int i = 0; i < 2; i++) {
        const int rowA = wm * 32 + i * 16 + lr + (grp & 1) * 8;
        baseA[i] = (uint32_t)rowA * 128;
    }
#pragma unroll
    for (int j2 = 0; j2 < 4; j2++) {
        const int rowB = wn * 64 + j2 * 16 + lr + (grp >> 1) * 8;
        baseB[j2] = (uint32_t)rowB * 128;
    }

    float acc[2][8][4];
#pragma unroll
    for (int i = 0; i < 2; i++)
#pragma unroll
        for (int j = 0; j < 8; j++)
#pragma unroll
            for (int v = 0; v < 4; v++) acc[i][j][v] = 0.f;

    load_chunk(0, 0);
    CP_ASYNC_COMMIT();

#pragma unroll
    for (int c = 0; c < 4; c++) {
        if (c < 3) { load_chunk(c + 1, (c + 1) & 1); CP_ASYNC_COMMIT(); }
        if (c < 3) CP_ASYNC_WAIT(1); else CP_ASYNC_WAIT(0);
        __syncthreads();

        const uint32_t sb = st_u32 + (uint32_t)(c & 1) * GEMM_STAGE_BYTES;
        const uint32_t Ah = sb, Al = sb + 16384, Bh = sb + 32768, Bl = sb + 49152;

#pragma unroll
        for (int ks = 0; ks < 4; ks++) {
            const uint32_t offA = (((uint32_t)ks * 32) + koffA) ^ xr16;
            const uint32_t offB = (((uint32_t)ks * 32) + koffB) ^ xr16;
            uint32_t ah[2][4], al[2][4], bh[4][4], bl[4][4];
#pragma unroll
            for (int i = 0; i < 2; i++) {
                ldm4(ah[i], Ah + baseA[i] + offA);
                ldm4(al[i], Al + baseA[i] + offA);
            }
#pragma unroll
            for (int j2 = 0; j2 < 4; j2++) {
                ldm4(bh[j2], Bh + baseB[j2] + offB);
                ldm4(bl[j2], Bl + baseB[j2] + offB);
            }
#pragma unroll
            for (int i = 0; i < 2; i++)
#pragma unroll
                for (int j = 0; j < 8; j++) {
                    const int j2 = j >> 1, sel = (j & 1) * 2;
                    mma16816(acc[i][j], ah[i], bh[j2][sel], bh[j2][sel + 1]);
                    mma16816(acc[i][j], ah[i], bl[j2][sel], bl[j2][sel + 1]);
                    mma16816(acc[i][j], al[i], bh[j2][sel], bh[j2][sel + 1]);
                }
        }
        __syncthreads();
    }

    const int mrow0 = mt + wm * 32 + (lane >> 2);
    const int qcol0 = q0 + wn * 64 + (lane & 3) * 2;
#pragma unroll
    for (int i = 0; i < 2; i++) {
#pragma unroll
        for (int j = 0; j < 8; j++) {
            const int q  = qcol0 + j * 8;
            const float bx = bias_s[q - q0], by = bias_s[q - q0 + 1];
#pragma unroll
            for (int half = 0; half < 2; half++) {
                const int m  = mrow0 + i * 16 + half * 8;
                const int bb = m & 63, tt = m >> 6;
                float2 v;
                v.x = acc[i][j][half * 2 + 0] + bx;
                v.y = acc[i][j][half * 2 + 1] + by;
                *reinterpret_cast<float2*>(
                    g_Z + (((size_t)dir * 512 + tt) * 64 + bb) * 1024 + q) = v;
            }
        }
    }
}

// ---------------------------------------------------------------------------
// Recurrence — warp-specialized chains. 512 threads: warps 0-7 run chain A,
// warps 8-15 run chain B, fully decoupled via named barriers (1 / 2). Each
// half executes the R13-proven turn (mbar wait -> GEMM -> gates -> staged
// ST.128 broadcast -> arrive) for its own chain only; the two halves'
// serial costs overlap each other's tensor work.
// 64 CTAs = 2 dirs x 4 bgroups(16) x 8 cluster ranks.
// SMEM: Whi 64K | Wlo 64K | A[2 ch][2 buf][hi 8K|lo 8K] 64K | mask 8K | bars
//       | stage[2 ch] 2K.
// ---------------------------------------------------------------------------
#define RP_WHI    0
#define RP_WLO    65536
#define RP_A      131072
#define RP_MASK   196608
#define RP_BAR    204800
#define RP_STAGE  204864
#define RP_SMEM   206912

__global__ void __cluster_dims__(8, 1, 1) __launch_bounds__(512, 1)
lstm_rec_kernel(const float* __restrict__ Wr_f, const float* __restrict__ Wr_b,
                float* __restrict__ out)
{
    extern __shared__ char smr[];
    const uint32_t sbase = smem_u32(smr);
    unsigned char* m_s = reinterpret_cast<unsigned char*>(smr + RP_MASK);

    const int tid  = threadIdx.x;
    const int bx   = blockIdx.x;
    const int dir  = bx >> 5;
    const int bgrp = (bx >> 3) & 3;
    const int rank = bx & 7;

    const int ch   = tid >> 8;                 // 0 = chain A, 1 = chain B
    const int ltid = tid & 255;
    const int w    = ltid >> 5, lane = ltid & 31;
    const int b    = lane >> 2;
    const int q    = lane & 3;
    const int mg   = lane >> 3, lr = lane & 7;

    const int u_l  = 4 * w + (q >> 1) + 2 * (q & 1);
    const int ug   = (rank << 5) + u_l;

    // --- one-time init (all 512 threads) ---------------------------------
    const float* Wr = dir ? Wr_b : Wr_f;
    for (int i = tid; i < 32768; i += 512) {
        const int n = i & 127;
        const int k = i >> 7;
        const float v = __ldg(&Wr[k * 1024 + (n & 3) * 256 + (rank << 5) + (n >> 2)]);
        __nv_bfloat16 hi, lo;
        split_bf16(v, hi, lo);
        const uint32_t off = swz512((uint32_t)n, (uint32_t)(k * 2));
        *reinterpret_cast<__nv_bfloat16*>(smr + RP_WHI + off) = hi;
        *reinterpret_cast<__nv_bfloat16*>(smr + RP_WLO + off) = lo;
    }
    for (int i = tid; i < 4096; i += 512)
        reinterpret_cast<float4*>(smr + RP_A)[i] = make_float4(0.f, 0.f, 0.f, 0.f);
    for (int i = tid; i < 16 * 512; i += 512)
        m_s[i] = g_mask[(bgrp * 16 + (i >> 9)) * 512 + (i & 511)];
    if (tid == 0) {
        MBARRIER_INIT(sbase + RP_BAR + 0, 8);
        MBARRIER_INIT(sbase + RP_BAR + 8, 8);
        MBARRIER_INIT(sbase + RP_BAR + 16, 8);
        MBARRIER_INIT(sbase + RP_BAR + 24, 8);
    }
    __syncthreads();
    CLUSTER_SYNC();

    // Remote bar base: ltid<8 of each half arms its own chain's barriers.
    uint32_t rbar = 0;
    if (ltid < 8) {
        rbar = mapa_rank(sbase + RP_BAR, (uint32_t)ltid);
        MBAR_ARRIVE_REL_CLUSTER(rbar + ch * 16);      // pre-arm this chain buf0
    }

    // Staged-broadcast mapping (per half): warp w copies stage -> rank w.
    const uint32_t stg = sbase + RP_STAGE + (uint32_t)ch * 1024;
    const int cp_b = lane >> 2;
    const int cp_j = lane & 3;
    const uint32_t cp_swz = swz512((uint32_t)cp_b, (uint32_t)(rank * 64 + cp_j * 16));
    const uint32_t cp_dst = mapa_rank(sbase + RP_A, (uint32_t)w) + cp_swz;
    const uint32_t cp_src = stg + (uint32_t)lane * 16;
    const uint32_t st_word = stg + ((uint32_t)(b * 16 + 2 * w + q) << 2);

    const uint32_t rowA  = (uint32_t)(lr + (mg & 1) * 8);
    const uint32_t koffA = (uint32_t)((mg >> 1) * 16);
    const uint32_t rowB  = (uint32_t)(w * 16 + lr + (mg >> 1) * 8);
    const uint32_t koffB = (uint32_t)((mg & 1) * 16);
    const uint32_t swA   = (uint32_t)lr << 4;
    const uint32_t baseBhi = sbase + RP_WHI + rowB * 512;
    const uint32_t baseBlo = sbase + RP_WLO + rowB * 512;

    const float4* Z4 = reinterpret_cast<const float4*>(g_Z);
    const int t0 = dir ? 511 : 0;
    const int barid = 1 + ch;

    float cst = 0.f, hprev = 0.f, hlast = 0.f;
    const int bg = bgrp * 16 + ch * 8 + b;
    float4 zn = __ldg(&Z4[(((size_t)dir * 512 + t0) * 64 + bg) * 256 + ug]);

    for (int step = 0; step < 512; step++) {
        const int t   = dir ? (511 - step) : step;
        const int cur = step & 1;
        const int nxt = cur ^ 1;
        const uint32_t par = (uint32_t)(step >> 1) & 1u;

        MBAR_WAIT_ACQ_CLUSTER(sbase + RP_BAR + ch * 16 + cur * 8, par);

        const float4 zin = zn;
        if (step < 511) {
            const int tn = dir ? (510 - step) : (step + 1);
            zn = __ldg(&Z4[(((size_t)dir * 512 + tn) * 64 + bg) * 256 + ug]);
        }

        // ---- tensor GEMM (this chain's tile only) ------------------------
        const uint32_t abase = sbase + RP_A + (uint32_t)ch * 32768
                             + (uint32_t)cur * 16384;
        const uint32_t baseAhi = abase + rowA * 512;
        const uint32_t baseAlo = baseAhi + 8192;
        float a0[4] = {0.f, 0.f, 0.f, 0.f};
        float b0[4] = {0.f, 0.f, 0.f, 0.f};
        float c0v[4] = {0.f, 0.f, 0.f, 0.f};
        float a1[4] = {0.f, 0.f, 0.f, 0.f};
        float b1[4] = {0.f, 0.f, 0.f, 0.f};
        float c1v[4] = {0.f, 0.f, 0.f, 0.f};
#pragma unroll
        for (int kt = 0; kt < 16; kt++) {
            const uint32_t kbA = (uint32_t)kt * 32 + koffA;
            const uint32_t kbB = (uint32_t)kt * 32 + koffB;
            const uint32_t offA = (kbA & 0x180u) + ((kbA & 0x70u) ^ swA);
            const uint32_t offB = (kbB & 0x180u) + ((kbB & 0x70u) ^ swA);
            uint32_t ah[4], al[4], bh[4], bl[4];
            ldm4(ah, baseAhi + offA);
            ldm4(al, baseAlo + offA);
            ldm4(bh, baseBhi + offB);
            ldm4(bl, baseBlo + offB);
            mma16816(a0, ah, bh[0], bh[1]);
            mma16816(b0, ah, bl[0], bl[1]);
            mma16816(c0v, al, bh[0], bh[1]);
            mma16816(a1, ah, bh[2], bh[3]);
            mma16816(b1, ah, bl[2], bl[3]);
            mma16816(c1v, al, bh[2], bh[3]);
        }
        const float c0 = a0[0] + b0[0] + c0v[0];
        const float c1 = a0[1] + b0[1] + c0v[1];
        const float d0 = a1[0] + b1[0] + c1v[0];
        const float d1 = a1[1] + b1[1] + c1v[1];

        // ---- gates -------------------------------------------------------
        const bool odd = (q & 1) != 0;
        const float s0 = odd ? c0 : d0;
        const float s1 = odd ? c1 : d1;
        const float r0 = __shfl_xor_sync(0xffffffffu, s0, 1);
        const float r1 = __shfl_xor_sync(0xffffffffu, s1, 1);
        float zi = (odd ? r0 : c0) + zin.x;
        float zf = (odd ? r1 : c1) + zin.y;
        float zc = (odd ? d0 : r0) + zin.z;
        float zo = (odd ? d1 : r1) + zin.w;

        const float gi = ftanh(zi);
        const float gf = ftanh(zf);
        const float gc = ftanh(zc);
        const float go = ftanh(zo);
        const float cn = fmaf(gf, cst, gi * gc);
        const float hn = go * ftanh(cn);

        const int  mrow = ch * 8 + b;
        const bool mk = m_s[(mrow << 9) + t] != 0;
        const float hv = mk ? hn : hprev;
        cst = mk ? cn : cst;
        hprev = hv;
        hlast = hv;

        // ---- stage packed bf16 hi/lo words -------------------------------
        const float hvp = __shfl_xor_sync(0xffffffffu, hv, 2);
        if (q < 2) {
            __nv_bfloat16 he, le, ho, lo2;
            split_bf16(hv,  he, le);
            split_bf16(hvp, ho, lo2);
            const uint32_t wh = (uint32_t)*reinterpret_cast<unsigned short*>(&he)
                              | ((uint32_t)*reinterpret_cast<unsigned short*>(&ho) << 16);
            const uint32_t wl = (uint32_t)*reinterpret_cast<unsigned short*>(&le)
                              | ((uint32_t)*reinterpret_cast<unsigned short*>(&lo2) << 16);
            asm volatile("st.shared.u32 [%0], %1;" :: "r"(st_word), "r"(wh) : "memory");
            asm volatile("st.shared.u32 [%0], %1;" :: "r"(st_word + 512), "r"(wl) : "memory");
        }
        NAMED_BAR(barid, 256);          // stage complete (this half only)

        // ---- wide remote copy: warp w -> remote rank w -------------------
        {
            const uint32_t bo = (uint32_t)ch * 32768 + (uint32_t)nxt * 16384;
            uint4 vh, vl;
            asm volatile("ld.shared.v4.b32 {%0,%1,%2,%3}, [%4];"
                         : "=r"(vh.x), "=r"(vh.y), "=r"(vh.z), "=r"(vh.w)
                         : "r"(cp_src));
            asm volatile("ld.shared.v4.b32 {%0,%1,%2,%3}, [%4];"
                         : "=r"(vl.x), "=r"(vl.y), "=r"(vl.z), "=r"(vl.w)
                         : "r"(cp_src + 512));
            ST_CLUSTER_U128(cp_dst + bo, vh);
            ST_CLUSTER_U128(cp_dst + bo + 8192, vl);
        }
        NAMED_BAR(barid, 256);          // all remote stores issued (this half)
        if (ltid < 8)
            MBAR_ARRIVE_REL_CLUSTER(rbar + ch * 16 + nxt * 8);

        // gmem output off the critical path
        out[((size_t)bg * 512 + t) * 512 + (dir << 8) + ug] = hv;
    }

    out[16777216 + (size_t)bg * 512 + (dir << 8) + ug] = hlast;

    CLUSTER_SYNC();
}

// ---------------------------------------------------------------------------
// Launch
// ---------------------------------------------------------------------------
extern "C" void kernel_launch(void* const* d_in, const int* in_sizes, int n_in,
                              void* d_out, int out_size)
{
    const float* x    = (const float*)d_in[0];
    const float* Wk_f = (const float*)d_in[1];
    const float* Wr_f = (const float*)d_in[2];
    const float* b_f  = (const float*)d_in[3];
    const float* Wk_b = (const float*)d_in[4];
    const float* Wr_b = (const float*)d_in[5];
    const float* b_b  = (const float*)d_in[6];
    float* out = (float*)d_out;

    mask_kernel<<<4096, 256>>>(x);
    convert_x_kernel<<<8192, 256>>>(x);
    convert_w_kernel<<<2048, 256>>>(Wk_f, Wk_b);

    cudaFuncSetAttribute(gemm_mma_kernel,
                         cudaFuncAttributeMaxDynamicSharedMemorySize, GEMM_SMEM_BYTES);
    dim3 gg(256, 16);
    gemm_mma_kernel<<<gg, 256, GEMM_SMEM_BYTES>>>(b_f, b_b);

    cudaFuncSetAttribute(lstm_rec_kernel,
                         cudaFuncAttributeMaxDynamicSharedMemorySize, RP_SMEM);
    lstm_rec_kernel<<<64, 512, RP_SMEM>>>(Wr_f, Wr_b, out);
}